// round 16
// baseline (speedup 1.0000x reference)
#include <cuda_runtime.h>
#include <cuda_fp16.h>
#include <cstdint>
#include <cstddef>

#define HW     16384
#define WIMG   128
#define DIM    192
#define CDIM   576
#define NB     8
#define NHEAD  8
#define NBH    192      // NB * 3 * NHEAD
#define GSL    4        // gram split-K slices

// ---------------- scratch (device globals; no allocations allowed) ----------
__device__ __half g_wqkvh[CDIM*DIM];       // fp16 copy of W_qkv
__device__ __half g_qkvh [NB*CDIM*HW];
__device__ __half g_conv0h[NB*CDIM*HW];
__device__ __half g_conv1h[NB*CDIM*HW];
__device__ __half g_conv2h[NB*CDIM*HW];
__device__ float g_partG[NBH*GSL*48*48];   // gram partials (48x48 per slice)
__device__ __half g_Mh  [NB*DIM*CDIM];

// ======================= helpers ============================================
__device__ __forceinline__ uint32_t smem_u32(const void* p) {
    uint32_t a;
    asm("{ .reg .u64 t; cvta.to.shared.u64 t, %1; cvt.u32.u64 %0, t; }"
        : "=r"(a) : "l"(p));
    return a;
}
__device__ __forceinline__ void cp_async16(uint32_t dst, const void* src, int src_sz) {
    asm volatile("cp.async.ca.shared.global [%0], [%1], 16, %2;"
                 :: "r"(dst), "l"(src), "r"(src_sz));
}
#define CP_COMMIT()  asm volatile("cp.async.commit_group;" ::: "memory")
#define CP_WAIT(n)   asm volatile("cp.async.wait_group %0;" :: "n"(n) : "memory")

__device__ __forceinline__ uint32_t pack2(float a, float b) {
    __half2 h = __floats2half2_rn(a, b);
    return *reinterpret_cast<uint32_t*>(&h);
}
__device__ __forceinline__ void mma_f16(float d[4], const uint32_t a[4],
                                        uint32_t b0, uint32_t b1) {
    asm volatile(
        "mma.sync.aligned.m16n8k16.row.col.f32.f16.f16.f32 "
        "{%0,%1,%2,%3}, {%4,%5,%6,%7}, {%8,%9}, {%0,%1,%2,%3};"
        : "+f"(d[0]), "+f"(d[1]), "+f"(d[2]), "+f"(d[3])
        : "r"(a[0]), "r"(a[1]), "r"(a[2]), "r"(a[3]), "r"(b0), "r"(b1));
}
__device__ __forceinline__ void ldmatrix_x4(uint32_t r[4], uint32_t addr) {
    asm volatile("ldmatrix.sync.aligned.m8n8.x4.shared.b16 {%0,%1,%2,%3}, [%4];"
                 : "=r"(r[0]), "=r"(r[1]), "=r"(r[2]), "=r"(r[3]) : "r"(addr));
}
__device__ __forceinline__ void ldmatrix_x2(uint32_t& r0, uint32_t& r1, uint32_t addr) {
    asm volatile("ldmatrix.sync.aligned.m8n8.x2.shared.b16 {%0,%1}, [%2];"
                 : "=r"(r0), "=r"(r1) : "r"(addr));
}
__device__ __forceinline__ void ldmatrix_x2t(uint32_t& b0, uint32_t& b1, uint32_t addr) {
    asm volatile("ldmatrix.sync.aligned.m8n8.x2.trans.shared.b16 {%0,%1}, [%2];"
                 : "=r"(b0), "=r"(b1) : "r"(addr));
}
__device__ __forceinline__ void unp4(uint2 u, float* d) {
    float2 f0 = __half22float2(*reinterpret_cast<__half2*>(&u.x));
    float2 f1 = __half22float2(*reinterpret_cast<__half2*>(&u.y));
    d[0] = f0.x; d[1] = f0.y; d[2] = f1.x; d[3] = f1.y;
}

// ======================= fp16 conversion prep (W_qkv only) ===================
__global__ __launch_bounds__(256) void k_cvt(const float4* __restrict__ src,
                                             uint2* __restrict__ dst) {
    int i = blockIdx.x * 256 + threadIdx.x;
    float4 v = src[i];
    dst[i] = make_uint2(pack2(v.x, v.y), pack2(v.z, v.w));
}

// ======================= tensor GEMM (cp.async + ldmatrix + mma f16) ========
// MODE 0: g_qkvh[b,576,HW](fp16) = g_wqkvh[576,192] @ X[b,192,HW](fp32, inline cvt)
// MODE 1: out[b,192,HW](fp32)    = g_Mh[b,192,576] @ V[b,576,HW] (conv fp16)
// CTA: 192 thr = 6 warps (3m x 2n), tile M192 x N128, K chunks 32,
// __launch_bounds__(192,2) -> 2 CTAs/SM.
#define A_BUF_B  15360     // 192*80
#define B16_BUF  8704      // 32*272
#define B16_OFF  (3 * A_BUF_B)               // 46080
#define B32_BUF  16896     // 32*528 (fp32 staging, 132-float stride)
#define B32_OFF  (B16_OFF + 2 * B16_BUF)     // 63488
#define GEMM0_SMEM (B32_OFF + 2 * B32_BUF)   // 97280
#define GEMM1_SMEM (B16_OFF + 3 * B16_BUF)   // 72192

template <int MODE>
__global__ __launch_bounds__(192, 2) void k_mma_gemm(float* __restrict__ Cout,
                                                     const float* __restrict__ Xf) {
    constexpr int KTOT = MODE ? CDIM : DIM;
    constexpr int NC   = KTOT / 32;

    extern __shared__ __align__(16) char smc[];
    const uint32_t sb = smem_u32(smc);

    const int tid = threadIdx.x;
    const int m0  = blockIdx.x * 192;
    const int n0  = blockIdx.y * 128;
    const int b   = blockIdx.z;

    const int warp = tid >> 5, lane = tid & 31;
    const int gid = lane >> 2, tg = lane & 3;
    const int m_w = (warp >> 1) * 64;      // 0/64/128
    const int n_w = (warp & 1) * 64;       // 0/64

    const __half* Aptr = MODE ? (g_Mh + (size_t)b * DIM * CDIM) : g_wqkvh;

    auto fill = [&](int cc) {
        const int k0 = cc * 32;
        const uint32_t aB = sb + (cc % 3) * A_BUF_B;
        // A: 192 rows x 4 segs of 16B = 768 tasks
#pragma unroll
        for (int i = 0; i < 4; i++) {
            int tsk = tid + i * 192;
            int row = tsk >> 2, seg = tsk & 3;
            const __half* src = Aptr + (size_t)(m0 + row) * KTOT + k0 + seg * 8;
            cp_async16(aB + row * 80 + seg * 16, src, 16);
        }
        if (MODE == 0) {
            // B fp32 staging: 32 k rows x 32 segs of 16B = 1024 tasks
            const uint32_t bS = sb + B32_OFF + (cc & 1) * B32_BUF;
#pragma unroll
            for (int i = 0; i < 6; i++) {
                int tsk = tid + i * 192;
                if (tsk < 1024) {
                    int row = tsk >> 5, seg = tsk & 31;
                    const float* src = Xf + (size_t)(b * DIM + k0 + row) * HW
                                        + n0 + seg * 4;
                    cp_async16(bS + row * 528 + seg * 16, src, 16);
                }
            }
        } else {
            // B fp16 direct: 32 k rows x 16 segs of 16B = 512 tasks
            const uint32_t bB = sb + B16_OFF + (cc % 3) * B16_BUF;
#pragma unroll
            for (int i = 0; i < 3; i++) {
                int tsk = tid + i * 192;
                if (tsk < 512) {
                    int row = tsk >> 4, seg = tsk & 15;
                    int kg = k0 + row;
                    int br = (kg >= 384) ? 2 : (kg >= 192) ? 1 : 0;
                    int ch = kg - br * 192;
                    const __half* cv = (br == 0) ? g_conv0h : (br == 1) ? g_conv1h : g_conv2h;
                    const __half* src = cv + ((size_t)(b * CDIM + 384 + ch)) * HW
                                         + n0 + seg * 8;
                    cp_async16(bB + row * 272 + seg * 16, src, 16);
                }
            }
        }
    };

    float acc[4][8][4];
#pragma unroll
    for (int mt = 0; mt < 4; mt++)
#pragma unroll
        for (int nt = 0; nt < 8; nt++)
#pragma unroll
            for (int r = 0; r < 4; r++) acc[mt][nt][r] = 0.f;

    fill(0); CP_COMMIT();
    fill(1); CP_COMMIT();

#pragma unroll 1
    for (int cc = 0; cc < NC; cc++) {
        if (cc + 1 < NC) { CP_WAIT(1); } else { CP_WAIT(0); }
        __syncthreads();

        if (MODE == 0) {
            // cvt staging(cc&1) -> B16(cc&1)
            const float* stg = (const float*)(smc + B32_OFF + (cc & 1) * B32_BUF);
            char* b16p = smc + B16_OFF + (cc & 1) * B16_BUF;
#pragma unroll
            for (int i = 0; i < 3; i++) {
                int tsk = tid + i * 192;
                if (tsk < 512) {
                    int row = tsk >> 4, seg = tsk & 15;
                    const float* p = stg + row * 132 + seg * 8;
                    float4 f0 = *(const float4*)p;
                    float4 f1 = *(const float4*)(p + 4);
                    uint4 u = make_uint4(pack2(f0.x, f0.y), pack2(f0.z, f0.w),
                                         pack2(f1.x, f1.y), pack2(f1.z, f1.w));
                    *(uint4*)(b16p + row * 272 + seg * 16) = u;
                }
            }
            __syncthreads();
        }
        if (cc + 2 < NC) { fill(cc + 2); CP_COMMIT(); }

        const uint32_t aB = sb + (cc % 3) * A_BUF_B;
        const uint32_t bB = sb + B16_OFF
                          + (MODE == 0 ? (cc & 1) : (cc % 3)) * B16_BUF;
#pragma unroll
        for (int k16 = 0; k16 < 2; k16++) {
            uint32_t a[4][4];
#pragma unroll
            for (int mt = 0; mt < 4; mt++) {
                uint32_t addr = aB + (m_w + mt * 16 + (lane & 15)) * 80
                              + k16 * 32 + ((lane >> 4) & 1) * 16;
                ldmatrix_x4(a[mt], addr);
            }
#pragma unroll
            for (int nt = 0; nt < 8; nt++) {
                uint32_t b0, b1;
                uint32_t baddr = bB + (k16 * 16 + (lane & 15)) * 272
                               + (n_w + nt * 8) * 2;
                ldmatrix_x2t(b0, b1, baddr);
#pragma unroll
                for (int mt = 0; mt < 4; mt++)
                    mma_f16(acc[mt][nt], a[mt], b0, b1);
            }
        }
    }

    if (MODE == 0) {
        __half* Cb = g_qkvh + (size_t)b * CDIM * HW;
#pragma unroll
        for (int mt = 0; mt < 4; mt++) {
            int r0 = m0 + m_w + mt * 16 + gid;
            int r1 = r0 + 8;
#pragma unroll
            for (int nt = 0; nt < 8; nt++) {
                int n = n0 + n_w + nt * 8 + tg * 2;
                *(uint32_t*)(Cb + (size_t)r0 * HW + n) = pack2(acc[mt][nt][0], acc[mt][nt][1]);
                *(uint32_t*)(Cb + (size_t)r1 * HW + n) = pack2(acc[mt][nt][2], acc[mt][nt][3]);
            }
        }
    } else {
        float* Cb = Cout + (size_t)b * DIM * HW;
#pragma unroll
        for (int mt = 0; mt < 4; mt++) {
            int r0 = m0 + m_w + mt * 16 + gid;
            int r1 = r0 + 8;
#pragma unroll
            for (int nt = 0; nt < 8; nt++) {
                int n = n0 + n_w + nt * 8 + tg * 2;
                *(float2*)(Cb + (size_t)r0 * HW + n) = make_float2(acc[mt][nt][0], acc[mt][nt][1]);
                *(float2*)(Cb + (size_t)r1 * HW + n) = make_float2(acc[mt][nt][2], acc[mt][nt][3]);
            }
        }
    }
}

// ---------------- smem-tiled depthwise 3x3, sliding y-window (fp16 tile) -----
#define CPAD_H 140
#define CROWS  134
#define CONV_SMEM_BYTES (CROWS * CPAD_H * 2)   // 37520

__device__ __forceinline__ void row3q(const float* row, const float* w,
                                      int D, float a[4]) {
#pragma unroll
    for (int x = 0; x < 4; x++)
        a[x] = fmaf(row[4 + x - D], w[0],
               fmaf(row[4 + x],     w[1],
               fmaf(row[4 + x + D], w[2], a[x])));
}
__device__ __forceinline__ void load_row_h(const __half* p, float row[12]) {
    unp4(*(const uint2*)p,       row);
    unp4(*(const uint2*)(p + 4), row + 4);
    unp4(*(const uint2*)(p + 8), row + 8);
}

__global__ __launch_bounds__(128) void k_dwconv(const float* __restrict__ w1,
                                                const float* __restrict__ w2,
                                                const float* __restrict__ w3) {
    extern __shared__ __align__(16) __half sph[];
    const int bc = blockIdx.x;              // b*576 + ch
    const int ch = bc % CDIM;
    const int tid = threadIdx.x;
    const __half* in = g_qkvh + (size_t)bc * HW;

    const uint2 z2 = make_uint2(0u, 0u);
    for (int i = tid; i < 105; i += 128) {
        int r = i / 35, c = (i % 35) * 4;
        *(uint2*)&sph[r * CPAD_H + c] = z2;
        *(uint2*)&sph[(131 + r) * CPAD_H + c] = z2;
    }
    for (int i = tid; i < 128; i += 128) {
        int r = 3 + i;
        *(uint2*)&sph[r * CPAD_H] = z2;
        *(uint2*)&sph[r * CPAD_H + 132] = z2;
        *(uint2*)&sph[r * CPAD_H + 136] = z2;
    }
    __syncthreads();

    for (int i = tid; i < HW / 4; i += 128) {
        int y = i >> 5, x = (i & 31) << 2;
        *(uint2*)&sph[(y + 3) * CPAD_H + x + 4] = *(const uint2*)(in + y * WIMG + x);
    }
    __syncthreads();

    float wr1[9], wr2[9], wr3[9];
#pragma unroll
    for (int i = 0; i < 9; i++) {
        wr1[i] = __ldg(w1 + ch * 9 + i);
        wr2[i] = __ldg(w2 + ch * 9 + i);
        wr3[i] = __ldg(w3 + ch * 9 + i);
    }

    __half* o0 = g_conv0h + (size_t)bc * HW;
    __half* o1 = g_conv1h + (size_t)bc * HW;
    __half* o2 = g_conv2h + (size_t)bc * HW;

#pragma unroll 1
    for (int task = tid; task < 608; task += 128) {
        const int x0 = (task & 31) << 2;
        const int y0 = (task >> 5) * 7;

        float win[7][12];
#pragma unroll
        for (int j = 0; j < 6; j++)
            load_row_h(sph + (y0 + j) * CPAD_H + x0, win[j]);

#pragma unroll
        for (int yy = 0; yy < 7; yy++) {
            const int y = y0 + yy;
            if (y < 128) {
                load_row_h(sph + (y0 + yy + 6) * CPAD_H + x0, win[(yy + 6) % 7]);

                float a1[4] = {0, 0, 0, 0}, a2[4] = {0, 0, 0, 0}, a3[4] = {0, 0, 0, 0};
                row3q(win[(yy + 2) % 7], wr1 + 0, 1, a1);
                row3q(win[(yy + 3) % 7], wr1 + 3, 1, a1);
                row3q(win[(yy + 4) % 7], wr1 + 6, 1, a1);
                row3q(win[(yy + 1) % 7], wr2 + 0, 2, a2);
                row3q(win[(yy + 3) % 7], wr2 + 3, 2, a2);
                row3q(win[(yy + 5) % 7], wr2 + 6, 2, a2);
                row3q(win[(yy + 0) % 7], wr3 + 0, 3, a3);
                row3q(win[(yy + 3) % 7], wr3 + 3, 3, a3);
                row3q(win[(yy + 6) % 7], wr3 + 6, 3, a3);

                const size_t ob = (size_t)y * WIMG + x0;
                *(uint2*)(o0 + ob) = make_uint2(pack2(a1[0], a1[1]), pack2(a1[2], a1[3]));
                *(uint2*)(o1 + ob) = make_uint2(pack2(a2[0], a2[1]), pack2(a2[2], a2[3]));
                *(uint2*)(o2 + ob) = make_uint2(pack2(a3[0], a3[1]), pack2(a3[2], a3[3]));
            }
        }
    }
}

// ---------------- Gram via tensor cores: G = [Q;K][Q;K]^T (48x48) ------------
#define GT_STRIDE_B 528                       // 264 halfs per row
#define GT_BYTES    (48 * GT_STRIDE_B)        // 25344
#define GACC_OFF    (3 * GT_BYTES)            // 76032
#define GRAM_SMEM   (GACC_OFF + 48 * 49 * 4)  // 85440

__global__ __launch_bounds__(256, 1) void k_gram() {
    extern __shared__ __align__(16) char gsm[];
    const uint32_t sb = smem_u32(gsm);
    const int bh = blockIdx.x;
    const int slice = blockIdx.y;
    const int b = bh / 24, rem = bh % 24;
    const int br = rem >> 3, head = rem & 7;
    const __half* conv = (br == 0) ? g_conv0h : (br == 1) ? g_conv1h : g_conv2h;
    const __half* qb = conv + (size_t)(b * CDIM + head * 24) * HW;
    const __half* kb = conv + (size_t)(b * CDIM + 192 + head * 24) * HW;

    const int tid = threadIdx.x;
    const int warp = tid >> 5, lane = tid & 31;
    const int col0s = slice * 4096;

    auto fill = [&](int it) {
        const int col0 = col0s + it * 256;
        const uint32_t tB = sb + (it % 3) * GT_BYTES;
#pragma unroll
        for (int i = 0; i < 6; i++) {
            int idx = tid + (i << 8);
            int row = idx >> 5, seg = idx & 31;
            const __half* src = ((row < 24) ? (qb + (size_t)row * HW)
                                            : (kb + (size_t)(row - 24) * HW))
                                + col0 + seg * 8;
            cp_async16(tB + row * GT_STRIDE_B + seg * 16, src, 16);
        }
    };

    float acc[3][6][4];
#pragma unroll
    for (int mt = 0; mt < 3; mt++)
#pragma unroll
        for (int nt = 0; nt < 6; nt++)
#pragma unroll
            for (int r = 0; r < 4; r++) acc[mt][nt][r] = 0.f;

    fill(0); CP_COMMIT();
    fill(1); CP_COMMIT();

#pragma unroll 1
    for (int it = 0; it < 16; it++) {
        if (it + 1 < 16) { CP_WAIT(1); } else { CP_WAIT(0); }
        __syncthreads();
        if (it + 2 < 16) { fill(it + 2); CP_COMMIT(); }

        const uint32_t tB = sb + (it % 3) * GT_BYTES;
#pragma unroll
        for (int c16 = 0; c16 < 2; c16++) {
            const uint32_t cb = warp * 64 + c16 * 32;
            uint32_t a[3][4];
#pragma unroll
            for (int mt = 0; mt < 3; mt++)
                ldmatrix_x4(a[mt], tB + (mt * 16 + (lane & 15)) * GT_STRIDE_B
                                     + cb + ((lane >> 4) & 1) * 16);
#pragma unroll
            for (int nt = 0; nt < 6; nt++) {
                uint32_t b0, b1;
                ldmatrix_x2(b0, b1, tB + (nt * 8 + (lane & 7)) * GT_STRIDE_B
                                      + cb + ((lane >> 3) & 1) * 16);
#pragma unroll
                for (int mt = 0; mt < 3; mt++)
                    mma_f16(acc[mt][nt], a[mt], b0, b1);
            }
        }
    }

    float* G = (float*)(gsm + GACC_OFF);
    for (int i = tid; i < 48 * 49; i += 256) G[i] = 0.f;
    __syncthreads();
    const int gr = lane >> 2, gc = (lane & 3) * 2;
#pragma unroll
    for (int mt = 0; mt < 3; mt++)
#pragma unroll
        for (int nt = 0; nt < 6; nt++) {
            int r = mt * 16 + gr, c = nt * 8 + gc;
            atomicAdd(&G[r * 49 + c],           acc[mt][nt][0]);
            atomicAdd(&G[r * 49 + c + 1],       acc[mt][nt][1]);
            atomicAdd(&G[(r + 8) * 49 + c],     acc[mt][nt][2]);
            atomicAdd(&G[(r + 8) * 49 + c + 1], acc[mt][nt][3]);
        }
    __syncthreads();
    float* outp = g_partG + (size_t)(bh * GSL + slice) * 2304;
    for (int i = tid; i < 2304; i += 256)
        outp[i] = G[(i / 48) * 49 + (i % 48)];
}

// ---------------- fused: reduce + normalize + softmax + proj-fold ------------
__global__ __launch_bounds__(576) void k_post(const float* __restrict__ temperature,
                                              const float* __restrict__ wproj) {
    const int bh = blockIdx.x;
    const int head = bh & 7;
    const int t = threadIdx.x;
    const int c = t / 24, d = t % 24;
    const float* Gp = g_partG + (size_t)bh * GSL * 2304;

    float s = 0.f;
#pragma unroll
    for (int sl = 0; sl < GSL; sl++)
        s += Gp[sl * 2304 + c * 48 + 24 + d];

    __shared__ float nq[24], nk[24], logits[576], rmax[24], rsum[24];
    __shared__ float att[576];
    if (t < 24) {
        float a = 0.f, b2 = 0.f;
#pragma unroll
        for (int sl = 0; sl < GSL; sl++) {
            a  += Gp[sl * 2304 + t * 48 + t];
            b2 += Gp[sl * 2304 + (24 + t) * 48 + 24 + t];
        }
        nq[t] = fmaxf(sqrtf(a),  1e-12f);
        nk[t] = fmaxf(sqrtf(b2), 1e-12f);
    }
    __syncthreads();
    float lg = s / (nq[c] * nk[d]) * temperature[head];
    logits[t] = lg;
    __syncthreads();
    if (d == 0) {
        float mx = -1e30f;
        for (int j = 0; j < 24; j++) mx = fmaxf(mx, logits[c * 24 + j]);
        float sm = 0.f;
        for (int j = 0; j < 24; j++) sm += expf(logits[c * 24 + j] - mx);
        rmax[c] = mx; rsum[c] = sm;
    }
    __syncthreads();
    att[t] = expf(lg - rmax[c]) / rsum[c];
    __syncthreads();

    if (t < DIM) {
        const int b  = bh / 24, rem = bh % 24;
        const int br = rem >> 3, hh = rem & 7;
        const int colbase = br * 192 + hh * 24;
        const float* wrow = wproj + (size_t)t * CDIM + colbase;
        __half* mrow = g_Mh + ((size_t)b * DIM + t) * CDIM + colbase;
        float wreg[24];
#pragma unroll
        for (int cc = 0; cc < 24; cc++) wreg[cc] = wrow[cc];
#pragma unroll 4
        for (int dd = 0; dd < 24; dd++) {
            float sm = 0.f;
#pragma unroll
            for (int cc = 0; cc < 24; cc++) sm = fmaf(wreg[cc], att[cc * 24 + dd], sm);
            mrow[dd] = __float2half_rn(sm);
        }
    }
}

// ---------------- launch ----------------------------------------------------
extern "C" void kernel_launch(void* const* d_in, const int* in_sizes, int n_in,
                              void* d_out, int out_size) {
    const float* x       = (const float*)d_in[0];
    const float* w_qkv   = (const float*)d_in[1];
    const float* w_dw1   = (const float*)d_in[2];
    const float* w_dw2   = (const float*)d_in[3];
    const float* w_dw3   = (const float*)d_in[4];
    const float* w_proj  = (const float*)d_in[5];
    const float* temp    = (const float*)d_in[6];
    float* out = (float*)d_out;

    cudaFuncSetAttribute(k_mma_gemm<0>, cudaFuncAttributeMaxDynamicSharedMemorySize,
                         GEMM0_SMEM);
    cudaFuncSetAttribute(k_mma_gemm<1>, cudaFuncAttributeMaxDynamicSharedMemorySize,
                         GEMM1_SMEM);
    cudaFuncSetAttribute(k_dwconv, cudaFuncAttributeMaxDynamicSharedMemorySize,
                         CONV_SMEM_BYTES);
    cudaFuncSetAttribute(k_gram, cudaFuncAttributeMaxDynamicSharedMemorySize,
                         GRAM_SMEM);

    __half* d_wh;    cudaGetSymbolAddress((void**)&d_wh, g_wqkvh);

    // fp16 prep: W_qkv only (110592 elems / 4 = 27648 tasks)
    k_cvt<<<108, 256>>>((const float4*)w_qkv, (uint2*)d_wh);

    // qkv = W_qkv @ X : 3 m-tiles x 128 n-tiles; X fp32 converted inline
    k_mma_gemm<0><<<dim3(3, 128, NB), 192, GEMM0_SMEM>>>(nullptr, x);
    k_dwconv<<<NB * CDIM, 128, CONV_SMEM_BYTES>>>(w_dw1, w_dw2, w_dw3);
    k_gram<<<dim3(NBH, GSL), 256, GRAM_SMEM>>>();
    k_post<<<NBH, 576>>>(temp, w_proj);
    // out = M_b @ V_b : 1 m-tile x 128 n-tiles
    k_mma_gemm<1><<<dim3(1, 128, NB), 192, GEMM1_SMEM>>>(out, nullptr);
}

// round 17
// speedup vs baseline: 1.0903x; 1.0903x over previous
#include <cuda_runtime.h>
#include <cuda_fp16.h>
#include <cstdint>
#include <cstddef>

#define HW     16384
#define WIMG   128
#define DIM    192
#define CDIM   576
#define NB     8
#define NHEAD  8
#define NBH    192      // NB * 3 * NHEAD
#define GSL    4        // gram split-K slices

// ---------------- scratch (device globals; no allocations allowed) ----------
__device__ __half g_xh   [NB*DIM*HW];      // fp16 copy of input X
__device__ __half g_wqkvh[CDIM*DIM];       // fp16 copy of W_qkv
__device__ __half g_qkvh [NB*CDIM*HW];
__device__ __half g_conv0h[NB*CDIM*HW];
__device__ __half g_conv1h[NB*CDIM*HW];
__device__ __half g_conv2h[NB*CDIM*HW];
__device__ float g_partG[NBH*GSL*48*48];   // gram partials (48x48 per slice)
__device__ __half g_Mh  [NB*DIM*CDIM];

// ======================= helpers ============================================
__device__ __forceinline__ uint32_t smem_u32(const void* p) {
    uint32_t a;
    asm("{ .reg .u64 t; cvta.to.shared.u64 t, %1; cvt.u32.u64 %0, t; }"
        : "=r"(a) : "l"(p));
    return a;
}
__device__ __forceinline__ void cp_async16(uint32_t dst, const void* src, int src_sz) {
    asm volatile("cp.async.ca.shared.global [%0], [%1], 16, %2;"
                 :: "r"(dst), "l"(src), "r"(src_sz));
}
#define CP_COMMIT()  asm volatile("cp.async.commit_group;" ::: "memory")
#define CP_WAIT(n)   asm volatile("cp.async.wait_group %0;" :: "n"(n) : "memory")

__device__ __forceinline__ uint32_t pack2(float a, float b) {
    __half2 h = __floats2half2_rn(a, b);
    return *reinterpret_cast<uint32_t*>(&h);
}
__device__ __forceinline__ void mma_f16(float d[4], const uint32_t a[4],
                                        uint32_t b0, uint32_t b1) {
    asm volatile(
        "mma.sync.aligned.m16n8k16.row.col.f32.f16.f16.f32 "
        "{%0,%1,%2,%3}, {%4,%5,%6,%7}, {%8,%9}, {%0,%1,%2,%3};"
        : "+f"(d[0]), "+f"(d[1]), "+f"(d[2]), "+f"(d[3])
        : "r"(a[0]), "r"(a[1]), "r"(a[2]), "r"(a[3]), "r"(b0), "r"(b1));
}
__device__ __forceinline__ void ldmatrix_x4(uint32_t r[4], uint32_t addr) {
    asm volatile("ldmatrix.sync.aligned.m8n8.x4.shared.b16 {%0,%1,%2,%3}, [%4];"
                 : "=r"(r[0]), "=r"(r[1]), "=r"(r[2]), "=r"(r[3]) : "r"(addr));
}
__device__ __forceinline__ void ldmatrix_x2(uint32_t& r0, uint32_t& r1, uint32_t addr) {
    asm volatile("ldmatrix.sync.aligned.m8n8.x2.shared.b16 {%0,%1}, [%2];"
                 : "=r"(r0), "=r"(r1) : "r"(addr));
}
__device__ __forceinline__ void ldmatrix_x2t(uint32_t& b0, uint32_t& b1, uint32_t addr) {
    asm volatile("ldmatrix.sync.aligned.m8n8.x2.trans.shared.b16 {%0,%1}, [%2];"
                 : "=r"(b0), "=r"(b1) : "r"(addr));
}
__device__ __forceinline__ void unp4(uint2 u, float* d) {
    float2 f0 = __half22float2(*reinterpret_cast<__half2*>(&u.x));
    float2 f1 = __half22float2(*reinterpret_cast<__half2*>(&u.y));
    d[0] = f0.x; d[1] = f0.y; d[2] = f1.x; d[3] = f1.y;
}

// ======================= fp16 conversion prep ================================
__global__ __launch_bounds__(256) void k_cvt(const float4* __restrict__ src,
                                             uint2* __restrict__ dst) {
    int i = blockIdx.x * 256 + threadIdx.x;
    float4 v = src[i];
    dst[i] = make_uint2(pack2(v.x, v.y), pack2(v.z, v.w));
}

// ======================= tensor GEMM (cp.async + ldmatrix + mma f16) ========
// MODE 0: g_qkvh[b,576,HW](fp16) = g_wqkvh[576,192] @ g_xh[b,192,HW]
// MODE 1: out[b,192,HW](fp32)    = g_Mh[b,192,576] @ V[b,576,HW] (conv v-halves)
// CTA: 192 thr = 6 warps (3m x 2n), tile M192 x N128, K chunks 32, 3-stage,
// __launch_bounds__(192,2) -> 2 CTAs/SM.
#define A_BUF_B 15360     // 192*80
#define B_BUF_B 8704      // 32*272
#define GEMM_SMEM_BYTES (3 * (A_BUF_B + B_BUF_B))   // 72192

template <int MODE>
__global__ __launch_bounds__(192, 2) void k_mma_gemm(float* __restrict__ Cout) {
    constexpr int KTOT = MODE ? CDIM : DIM;
    constexpr int NC   = KTOT / 32;

    extern __shared__ __align__(16) char smc[];
    const uint32_t sb = smem_u32(smc);

    const int tid = threadIdx.x;
    const int m0  = blockIdx.x * 192;
    const int n0  = blockIdx.y * 128;
    const int b   = blockIdx.z;

    const int warp = tid >> 5, lane = tid & 31;
    const int gid = lane >> 2, tg = lane & 3;
    const int m_w = (warp >> 1) * 64;      // 0/64/128
    const int n_w = (warp & 1) * 64;       // 0/64

    const __half* Aptr = MODE ? (g_Mh + (size_t)b * DIM * CDIM) : g_wqkvh;

    auto fill = [&](int cc) {
        const int k0 = cc * 32;
        const uint32_t aB = sb + (cc % 3) * A_BUF_B;
        const uint32_t bB = sb + 3 * A_BUF_B + (cc % 3) * B_BUF_B;
#pragma unroll
        for (int i = 0; i < 4; i++) {
            int tsk = tid + i * 192;
            int row = tsk >> 2, seg = tsk & 3;
            const __half* src = Aptr + (size_t)(m0 + row) * KTOT + k0 + seg * 8;
            cp_async16(aB + row * 80 + seg * 16, src, 16);
        }
#pragma unroll
        for (int i = 0; i < 3; i++) {
            int tsk = tid + i * 192;
            if (tsk < 512) {
                int row = tsk >> 4, seg = tsk & 15;
                int kg = k0 + row;
                const __half* src;
                if (MODE == 0) {
                    src = g_xh + ((size_t)(b * DIM + kg)) * HW + n0 + seg * 8;
                } else {
                    int br = (kg >= 384) ? 2 : (kg >= 192) ? 1 : 0;
                    int ch = kg - br * 192;
                    const __half* cv = (br == 0) ? g_conv0h : (br == 1) ? g_conv1h : g_conv2h;
                    src = cv + ((size_t)(b * CDIM + 384 + ch)) * HW + n0 + seg * 8;
                }
                cp_async16(bB + row * 272 + seg * 16, src, 16);
            }
        }
    };

    float acc[4][8][4];
#pragma unroll
    for (int mt = 0; mt < 4; mt++)
#pragma unroll
        for (int nt = 0; nt < 8; nt++)
#pragma unroll
            for (int r = 0; r < 4; r++) acc[mt][nt][r] = 0.f;

    fill(0); CP_COMMIT();
    fill(1); CP_COMMIT();

#pragma unroll 1
    for (int cc = 0; cc < NC; cc++) {
        if (cc + 1 < NC) { CP_WAIT(1); } else { CP_WAIT(0); }
        __syncthreads();
        if (cc + 2 < NC) { fill(cc + 2); CP_COMMIT(); }

        const uint32_t aB = sb + (cc % 3) * A_BUF_B;
        const uint32_t bB = sb + 3 * A_BUF_B + (cc % 3) * B_BUF_B;
#pragma unroll
        for (int k16 = 0; k16 < 2; k16++) {
            uint32_t a[4][4];
#pragma unroll
            for (int mt = 0; mt < 4; mt++) {
                uint32_t addr = aB + (m_w + mt * 16 + (lane & 15)) * 80
                              + k16 * 32 + ((lane >> 4) & 1) * 16;
                ldmatrix_x4(a[mt], addr);
            }
#pragma unroll
            for (int nt = 0; nt < 8; nt++) {
                uint32_t b0, b1;
                uint32_t baddr = bB + (k16 * 16 + (lane & 15)) * 272
                               + (n_w + nt * 8) * 2;
                ldmatrix_x2t(b0, b1, baddr);
#pragma unroll
                for (int mt = 0; mt < 4; mt++)
                    mma_f16(acc[mt][nt], a[mt], b0, b1);
            }
        }
    }

    if (MODE == 0) {
        __half* Cb = g_qkvh + (size_t)b * CDIM * HW;
#pragma unroll
        for (int mt = 0; mt < 4; mt++) {
            int r0 = m0 + m_w + mt * 16 + gid;
            int r1 = r0 + 8;
#pragma unroll
            for (int nt = 0; nt < 8; nt++) {
                int n = n0 + n_w + nt * 8 + tg * 2;
                *(uint32_t*)(Cb + (size_t)r0 * HW + n) = pack2(acc[mt][nt][0], acc[mt][nt][1]);
                *(uint32_t*)(Cb + (size_t)r1 * HW + n) = pack2(acc[mt][nt][2], acc[mt][nt][3]);
            }
        }
    } else {
        float* Cb = Cout + (size_t)b * DIM * HW;
#pragma unroll
        for (int mt = 0; mt < 4; mt++) {
            int r0 = m0 + m_w + mt * 16 + gid;
            int r1 = r0 + 8;
#pragma unroll
            for (int nt = 0; nt < 8; nt++) {
                int n = n0 + n_w + nt * 8 + tg * 2;
                *(float2*)(Cb + (size_t)r0 * HW + n) = make_float2(acc[mt][nt][0], acc[mt][nt][1]);
                *(float2*)(Cb + (size_t)r1 * HW + n) = make_float2(acc[mt][nt][2], acc[mt][nt][3]);
            }
        }
    }
}

// ---------------- smem-tiled depthwise 3x3, sliding y-window (fp16 tile) -----
#define CPAD_H 140
#define CROWS  134
#define CONV_SMEM_BYTES (CROWS * CPAD_H * 2)   // 37520

__device__ __forceinline__ void row3q(const float* row, const float* w,
                                      int D, float a[4]) {
#pragma unroll
    for (int x = 0; x < 4; x++)
        a[x] = fmaf(row[4 + x - D], w[0],
               fmaf(row[4 + x],     w[1],
               fmaf(row[4 + x + D], w[2], a[x])));
}
__device__ __forceinline__ void load_row_h(const __half* p, float row[12]) {
    unp4(*(const uint2*)p,       row);
    unp4(*(const uint2*)(p + 4), row + 4);
    unp4(*(const uint2*)(p + 8), row + 8);
}

__global__ __launch_bounds__(128) void k_dwconv(const float* __restrict__ w1,
                                                const float* __restrict__ w2,
                                                const float* __restrict__ w3) {
    extern __shared__ __align__(16) __half sph[];
    const int bc = blockIdx.x;              // b*576 + ch
    const int ch = bc % CDIM;
    const int tid = threadIdx.x;
    const __half* in = g_qkvh + (size_t)bc * HW;

    const uint2 z2 = make_uint2(0u, 0u);
    for (int i = tid; i < 105; i += 128) {
        int r = i / 35, c = (i % 35) * 4;
        *(uint2*)&sph[r * CPAD_H + c] = z2;
        *(uint2*)&sph[(131 + r) * CPAD_H + c] = z2;
    }
    for (int i = tid; i < 128; i += 128) {
        int r = 3 + i;
        *(uint2*)&sph[r * CPAD_H] = z2;
        *(uint2*)&sph[r * CPAD_H + 132] = z2;
        *(uint2*)&sph[r * CPAD_H + 136] = z2;
    }
    __syncthreads();

    for (int i = tid; i < HW / 4; i += 128) {
        int y = i >> 5, x = (i & 31) << 2;
        *(uint2*)&sph[(y + 3) * CPAD_H + x + 4] = *(const uint2*)(in + y * WIMG + x);
    }
    __syncthreads();

    float wr1[9], wr2[9], wr3[9];
#pragma unroll
    for (int i = 0; i < 9; i++) {
        wr1[i] = __ldg(w1 + ch * 9 + i);
        wr2[i] = __ldg(w2 + ch * 9 + i);
        wr3[i] = __ldg(w3 + ch * 9 + i);
    }

    __half* o0 = g_conv0h + (size_t)bc * HW;
    __half* o1 = g_conv1h + (size_t)bc * HW;
    __half* o2 = g_conv2h + (size_t)bc * HW;

#pragma unroll 1
    for (int task = tid; task < 608; task += 128) {
        const int x0 = (task & 31) << 2;
        const int y0 = (task >> 5) * 7;

        float win[7][12];
#pragma unroll
        for (int j = 0; j < 6; j++)
            load_row_h(sph + (y0 + j) * CPAD_H + x0, win[j]);

#pragma unroll
        for (int yy = 0; yy < 7; yy++) {
            const int y = y0 + yy;
            if (y < 128) {
                load_row_h(sph + (y0 + yy + 6) * CPAD_H + x0, win[(yy + 6) % 7]);

                float a1[4] = {0, 0, 0, 0}, a2[4] = {0, 0, 0, 0}, a3[4] = {0, 0, 0, 0};
                row3q(win[(yy + 2) % 7], wr1 + 0, 1, a1);
                row3q(win[(yy + 3) % 7], wr1 + 3, 1, a1);
                row3q(win[(yy + 4) % 7], wr1 + 6, 1, a1);
                row3q(win[(yy + 1) % 7], wr2 + 0, 2, a2);
                row3q(win[(yy + 3) % 7], wr2 + 3, 2, a2);
                row3q(win[(yy + 5) % 7], wr2 + 6, 2, a2);
                row3q(win[(yy + 0) % 7], wr3 + 0, 3, a3);
                row3q(win[(yy + 3) % 7], wr3 + 3, 3, a3);
                row3q(win[(yy + 6) % 7], wr3 + 6, 3, a3);

                const size_t ob = (size_t)y * WIMG + x0;
                *(uint2*)(o0 + ob) = make_uint2(pack2(a1[0], a1[1]), pack2(a1[2], a1[3]));
                *(uint2*)(o1 + ob) = make_uint2(pack2(a2[0], a2[1]), pack2(a2[2], a2[3]));
                *(uint2*)(o2 + ob) = make_uint2(pack2(a3[0], a3[1]), pack2(a3[2], a3[3]));
            }
        }
    }
}

// ---------------- Gram via tensor cores: G = [Q;K][Q;K]^T (48x48) ------------
// 8 warps = 4 col-slices x 2 nt-halves -> acc 36 floats/thread -> 2 CTAs/SM.
#define GT_STRIDE_B 528                       // 264 halfs per row
#define GT_BYTES    (48 * GT_STRIDE_B)        // 25344
#define GACC_OFF    (3 * GT_BYTES)            // 76032
#define GRAM_SMEM   (GACC_OFF + 48 * 49 * 4)  // 85440

__global__ __launch_bounds__(256, 2) void k_gram() {
    extern __shared__ __align__(16) char gsm[];
    const uint32_t sb = smem_u32(gsm);
    const int bh = blockIdx.x;
    const int slice = blockIdx.y;
    const int b = bh / 24, rem = bh % 24;
    const int br = rem >> 3, head = rem & 7;
    const __half* conv = (br == 0) ? g_conv0h : (br == 1) ? g_conv1h : g_conv2h;
    const __half* qb = conv + (size_t)(b * CDIM + head * 24) * HW;
    const __half* kb = conv + (size_t)(b * CDIM + 192 + head * 24) * HW;

    const int tid = threadIdx.x;
    const int warp = tid >> 5, lane = tid & 31;
    const int cslice = warp & 3;            // 64-col slice
    const int nth = warp >> 2;              // nt half: 0 -> nt 0-2, 1 -> nt 3-5
    const int col0s = slice * 4096;

    auto fill = [&](int it) {
        const int col0 = col0s + it * 256;
        const uint32_t tB = sb + (it % 3) * GT_BYTES;
#pragma unroll
        for (int i = 0; i < 6; i++) {
            int idx = tid + (i << 8);
            int row = idx >> 5, seg = idx & 31;
            const __half* src = ((row < 24) ? (qb + (size_t)row * HW)
                                            : (kb + (size_t)(row - 24) * HW))
                                + col0 + seg * 8;
            cp_async16(tB + row * GT_STRIDE_B + seg * 16, src, 16);
        }
    };

    float acc[3][3][4];
#pragma unroll
    for (int mt = 0; mt < 3; mt++)
#pragma unroll
        for (int nt = 0; nt < 3; nt++)
#pragma unroll
            for (int r = 0; r < 4; r++) acc[mt][nt][r] = 0.f;

    fill(0); CP_COMMIT();
    fill(1); CP_COMMIT();

#pragma unroll 1
    for (int it = 0; it < 16; it++) {
        if (it + 1 < 16) { CP_WAIT(1); } else { CP_WAIT(0); }
        __syncthreads();
        if (it + 2 < 16) { fill(it + 2); CP_COMMIT(); }

        const uint32_t tB = sb + (it % 3) * GT_BYTES;
#pragma unroll
        for (int c16 = 0; c16 < 4; c16++) {
            const uint32_t cb = cslice * 128 + c16 * 32;   // bytes within row
            uint32_t a[3][4];
#pragma unroll
            for (int mt = 0; mt < 3; mt++)
                ldmatrix_x4(a[mt], tB + (mt * 16 + (lane & 15)) * GT_STRIDE_B
                                     + cb + ((lane >> 4) & 1) * 16);
#pragma unroll
            for (int nt = 0; nt < 3; nt++) {
                uint32_t b0, b1;
                ldmatrix_x2(b0, b1, tB + ((nth * 3 + nt) * 8 + (lane & 7)) * GT_STRIDE_B
                                      + cb + ((lane >> 3) & 1) * 16);
#pragma unroll
                for (int mt = 0; mt < 3; mt++)
                    mma_f16(acc[mt][nt], a[mt], b0, b1);
            }
        }
    }

    // reduce warps into smem G[48][49] (4-way atomic contention per cell)
    float* G = (float*)(gsm + GACC_OFF);
    for (int i = tid; i < 48 * 49; i += 256) G[i] = 0.f;
    __syncthreads();
    const int gr = lane >> 2, gc = (lane & 3) * 2;
#pragma unroll
    for (int mt = 0; mt < 3; mt++)
#pragma unroll
        for (int nt = 0; nt < 3; nt++) {
            int r = mt * 16 + gr, c = (nth * 3 + nt) * 8 + gc;
            atomicAdd(&G[r * 49 + c],           acc[mt][nt][0]);
            atomicAdd(&G[r * 49 + c + 1],       acc[mt][nt][1]);
            atomicAdd(&G[(r + 8) * 49 + c],     acc[mt][nt][2]);
            atomicAdd(&G[(r + 8) * 49 + c + 1], acc[mt][nt][3]);
        }
    __syncthreads();
    float* outp = g_partG + (size_t)(bh * GSL + slice) * 2304;
    for (int i = tid; i < 2304; i += 256)
        outp[i] = G[(i / 48) * 49 + (i % 48)];
}

// ---------------- fused: reduce + normalize + softmax + proj-fold ------------
__global__ __launch_bounds__(576) void k_post(const float* __restrict__ temperature,
                                              const float* __restrict__ wproj) {
    const int bh = blockIdx.x;
    const int head = bh & 7;
    const int t = threadIdx.x;
    const int c = t / 24, d = t % 24;
    const float* Gp = g_partG + (size_t)bh * GSL * 2304;

    float s = 0.f;
#pragma unroll
    for (int sl = 0; sl < GSL; sl++)
        s += Gp[sl * 2304 + c * 48 + 24 + d];

    __shared__ float nq[24], nk[24], logits[576], rmax[24], rsum[24];
    __shared__ float att[576];
    if (t < 24) {
        float a = 0.f, b2 = 0.f;
#pragma unroll
        for (int sl = 0; sl < GSL; sl++) {
            a  += Gp[sl * 2304 + t * 48 + t];
            b2 += Gp[sl * 2304 + (24 + t) * 48 + 24 + t];
        }
        nq[t] = fmaxf(sqrtf(a),  1e-12f);
        nk[t] = fmaxf(sqrtf(b2), 1e-12f);
    }
    __syncthreads();
    float lg = s / (nq[c] * nk[d]) * temperature[head];
    logits[t] = lg;
    __syncthreads();
    if (d == 0) {
        float mx = -1e30f;
        for (int j = 0; j < 24; j++) mx = fmaxf(mx, logits[c * 24 + j]);
        float sm = 0.f;
        for (int j = 0; j < 24; j++) sm += expf(logits[c * 24 + j] - mx);
        rmax[c] = mx; rsum[c] = sm;
    }
    __syncthreads();
    att[t] = expf(lg - rmax[c]) / rsum[c];
    __syncthreads();

    if (t < DIM) {
        const int b  = bh / 24, rem = bh % 24;
        const int br = rem >> 3, hh = rem & 7;
        const int colbase = br * 192 + hh * 24;
        const float* wrow = wproj + (size_t)t * CDIM + colbase;
        __half* mrow = g_Mh + ((size_t)b * DIM + t) * CDIM + colbase;
        float wreg[24];
#pragma unroll
        for (int cc = 0; cc < 24; cc++) wreg[cc] = wrow[cc];
#pragma unroll 4
        for (int dd = 0; dd < 24; dd++) {
            float sm = 0.f;
#pragma unroll
            for (int cc = 0; cc < 24; cc++) sm = fmaf(wreg[cc], att[cc * 24 + dd], sm);
            mrow[dd] = __float2half_rn(sm);
        }
    }
}

// ---------------- launch ----------------------------------------------------
extern "C" void kernel_launch(void* const* d_in, const int* in_sizes, int n_in,
                              void* d_out, int out_size) {
    const float* x       = (const float*)d_in[0];
    const float* w_qkv   = (const float*)d_in[1];
    const float* w_dw1   = (const float*)d_in[2];
    const float* w_dw2   = (const float*)d_in[3];
    const float* w_dw3   = (const float*)d_in[4];
    const float* w_proj  = (const float*)d_in[5];
    const float* temp    = (const float*)d_in[6];
    float* out = (float*)d_out;

    cudaFuncSetAttribute(k_mma_gemm<0>, cudaFuncAttributeMaxDynamicSharedMemorySize,
                         GEMM_SMEM_BYTES);
    cudaFuncSetAttribute(k_mma_gemm<1>, cudaFuncAttributeMaxDynamicSharedMemorySize,
                         GEMM_SMEM_BYTES);
    cudaFuncSetAttribute(k_dwconv, cudaFuncAttributeMaxDynamicSharedMemorySize,
                         CONV_SMEM_BYTES);
    cudaFuncSetAttribute(k_gram, cudaFuncAttributeMaxDynamicSharedMemorySize,
                         GRAM_SMEM);

    __half* d_xh;    cudaGetSymbolAddress((void**)&d_xh, g_xh);
    __half* d_wh;    cudaGetSymbolAddress((void**)&d_wh, g_wqkvh);

    k_cvt<<<24576, 256>>>((const float4*)x, (uint2*)d_xh);
    k_cvt<<<108, 256>>>((const float4*)w_qkv, (uint2*)d_wh);

    // qkv = W_qkv @ X : 3 m-tiles x 128 n-tiles
    k_mma_gemm<0><<<dim3(3, 128, NB), 192, GEMM_SMEM_BYTES>>>(nullptr);
    k_dwconv<<<NB * CDIM, 128, CONV_SMEM_BYTES>>>(w_dw1, w_dw2, w_dw3);
    k_gram<<<dim3(NBH, GSL), 256, GRAM_SMEM>>>();
    k_post<<<NBH, 576>>>(temp, w_proj);
    // out = M_b @ V_b : 1 m-tile x 128 n-tiles
    k_mma_gemm<1><<<dim3(1, 128, NB), 192, GEMM_SMEM_BYTES>>>(out);
}